// round 3
// baseline (speedup 1.0000x reference)
#include <cuda_runtime.h>
#include <math.h>

#define DM   1024
#define DI   2048
#define DS   16
#define DTR  64
#define BATCH 2
#define LSEQ 2048
#define ROWS (BATCH*LSEQ)          // 4096 token rows

// ---------------- scratch (device globals; no allocation allowed) ----------
__device__ float g_xz  [ROWS * 2 * DI];   // 4096 x 4096   (xi | z)
__device__ float g_xc  [ROWS * DI];       // conv+silu output (u)
__device__ float g_xdbl[ROWS * 96];       // dt_r(64) | B(16) | C(16)
__device__ float g_dt  [ROWS * DI];       // softplus(dt)
__device__ float g_y   [ROWS * DI];       // gated scan output
__device__ float g_o   [ROWS * DM];       // out_proj result (pre-LN)

// ---------------------------------------------------------------------------
// Generic tiled SGEMM:  C[M,N] = epi( A[M,K] * B[N,K]^T )   (both K-major)
// EPI 0: none.  EPI 1: softplus(v + bias[col])
// ---------------------------------------------------------------------------
template<int BM, int BN, int BK, int TM, int TN, int EPI>
__global__ void __launch_bounds__((BM/TM)*(BN/TN))
sgemm_nt(const float* __restrict__ A, int lda,
         const float* __restrict__ B, int ldb,
         float* __restrict__ C, int ldc,
         int K,
         const float* __restrict__ bias)
{
    constexpr int NT = (BM/TM)*(BN/TN);
    __shared__ float As[BK][BM];
    __shared__ float Bs[BK][BN];

    const int tid = threadIdx.x;
    const int tx  = tid % (BN/TN);
    const int ty  = tid / (BN/TN);
    const int rowBase = blockIdx.y * BM;
    const int colBase = blockIdx.x * BN;

    float acc[TM][TN];
#pragma unroll
    for (int i = 0; i < TM; i++)
#pragma unroll
        for (int j = 0; j < TN; j++) acc[i][j] = 0.f;

    for (int k0 = 0; k0 < K; k0 += BK) {
        // A tile -> As (transposed to [BK][BM])
#pragma unroll 2
        for (int i = tid; i < BM*BK/4; i += NT) {
            int r  = i / (BK/4);
            int kq = (i % (BK/4)) * 4;
            float4 v = *reinterpret_cast<const float4*>(&A[(rowBase + r)*lda + k0 + kq]);
            As[kq+0][r] = v.x; As[kq+1][r] = v.y; As[kq+2][r] = v.z; As[kq+3][r] = v.w;
        }
        // B tile -> Bs
#pragma unroll 2
        for (int i = tid; i < BN*BK/4; i += NT) {
            int r  = i / (BK/4);
            int kq = (i % (BK/4)) * 4;
            float4 v = *reinterpret_cast<const float4*>(&B[(colBase + r)*ldb + k0 + kq]);
            Bs[kq+0][r] = v.x; Bs[kq+1][r] = v.y; Bs[kq+2][r] = v.z; Bs[kq+3][r] = v.w;
        }
        __syncthreads();

#pragma unroll
        for (int kk = 0; kk < BK; kk++) {
            float a[TM], b[TN];
#pragma unroll
            for (int i = 0; i < TM; i++) a[i] = As[kk][ty*TM + i];
#pragma unroll
            for (int j = 0; j < TN; j++) b[j] = Bs[kk][tx*TN + j];
#pragma unroll
            for (int i = 0; i < TM; i++)
#pragma unroll
                for (int j = 0; j < TN; j++)
                    acc[i][j] = fmaf(a[i], b[j], acc[i][j]);
        }
        __syncthreads();
    }

#pragma unroll
    for (int i = 0; i < TM; i++) {
        int r = rowBase + ty*TM + i;
#pragma unroll
        for (int j = 0; j < TN; j++) {
            int c = colBase + tx*TN + j;
            float v = acc[i][j];
            if (EPI == 1) {
                v += bias[c];
                // stable softplus: max(v,0) + log1p(exp(-|v|))
                v = fmaxf(v, 0.f) + log1pf(__expf(-fabsf(v)));
            }
            C[r*ldc + c] = v;
        }
    }
}

// ---------------------------------------------------------------------------
// Depthwise causal conv (k=4) + bias + SiLU.  Reads xi = g_xz[:, :DI].
// ---------------------------------------------------------------------------
__global__ void conv_silu_kernel(const float* __restrict__ cw,
                                 const float* __restrict__ cb)
{
    int idx = blockIdx.x * blockDim.x + threadIdx.x;
    if (idx >= ROWS * DI) return;
    int d = idx % DI;
    int t = (idx / DI) % LSEQ;
    int b = idx / (DI * LSEQ);
    float acc = cb[d];
#pragma unroll
    for (int j = 0; j < 4; j++) {
        int tt = t - 3 + j;
        if (tt >= 0)
            acc = fmaf(cw[d*4 + j], g_xz[(b*LSEQ + tt)*(2*DI) + d], acc);
    }
    g_xc[idx] = acc / (1.f + __expf(-acc));   // silu
}

// ---------------------------------------------------------------------------
// Selective scan. 4 threads per channel, 4 states per thread.
// Block = 256 threads = 64 channels of one batch. Grid = 2*32 = 64 blocks.
// Fuses y = (scan_y + D*u) * silu(z) epilogue.
// ---------------------------------------------------------------------------
__global__ void __launch_bounds__(256)
scan_kernel(const float* __restrict__ Alog, const float* __restrict__ Dv)
{
    const int b     = blockIdx.x >> 5;          // 32 blocks per batch
    const int dBase = (blockIdx.x & 31) * 64;
    const int tid   = threadIdx.x;
    const int d     = dBase + (tid >> 2);
    const int j     = tid & 3;                  // state group (4 states)

    float A[4];
#pragma unroll
    for (int s = 0; s < 4; s++) A[s] = -__expf(Alog[d*DS + j*4 + s]);

    float h[4] = {0.f, 0.f, 0.f, 0.f};
    const float Dd = Dv[d];

    __shared__ float sB[64][16];
    __shared__ float sC[64][16];

    const float* __restrict__ xdbl = g_xdbl + b*LSEQ*96;
    const float* __restrict__ dtp  = g_dt   + b*LSEQ*DI;
    const float* __restrict__ up   = g_xc   + b*LSEQ*DI;
    const float* __restrict__ zp   = g_xz   + b*LSEQ*(2*DI) + DI;
    float*       __restrict__ yp   = g_y    + b*LSEQ*DI;

    for (int t0 = 0; t0 < LSEQ; t0 += 64) {
        __syncthreads();
        // stage B,C chunk (64 steps x 32 vals)
        for (int i = tid; i < 64*32; i += 256) {
            int tl = i >> 5, c = i & 31;
            float v = xdbl[(t0 + tl)*96 + 64 + c];
            if (c < 16) sB[tl][c] = v; else sC[tl][c - 16] = v;
        }
        __syncthreads();

#pragma unroll 4
        for (int tl = 0; tl < 64; tl++) {
            const int t  = t0 + tl;
            const float dt = dtp[t*DI + d];
            const float u  = up [t*DI + d];
            const float du = dt * u;
            float acc = 0.f;
#pragma unroll
            for (int s = 0; s < 4; s++) {
                float dA = __expf(dt * A[s]);
                h[s] = fmaf(dA, h[s], du * sB[tl][j*4 + s]);
                acc  = fmaf(h[s], sC[tl][j*4 + s], acc);
            }
            acc += __shfl_xor_sync(0xffffffffu, acc, 1);
            acc += __shfl_xor_sync(0xffffffffu, acc, 2);
            if (j == 0) {
                float z  = zp[t*(2*DI) + d];
                float yv = fmaf(Dd, u, acc);
                yv *= z / (1.f + __expf(-z));      // * silu(z)
                yp[t*DI + d] = yv;
            }
        }
    }
}

// ---------------------------------------------------------------------------
// Residual + LayerNorm over 1024.  out = LN(g_o + x) * g + b
// ---------------------------------------------------------------------------
__global__ void __launch_bounds__(256)
ln_kernel(const float* __restrict__ x, const float* __restrict__ gw,
          const float* __restrict__ gb, float* __restrict__ out)
{
    const int row = blockIdx.x;
    const int tid = threadIdx.x;
    const float* o  = g_o + row*DM;
    const float* xr = x   + row*DM;

    float v[4];
    float s = 0.f;
#pragma unroll
    for (int i = 0; i < 4; i++) {
        int c = tid + 256*i;
        v[i] = o[c] + xr[c];
        s += v[i];
    }
    __shared__ float red[8];
    __shared__ float sMean, sVar;
#pragma unroll
    for (int off = 16; off; off >>= 1) s += __shfl_xor_sync(0xffffffffu, s, off);
    if ((tid & 31) == 0) red[tid >> 5] = s;
    __syncthreads();
    if (tid == 0) {
        float t = 0.f;
        for (int i = 0; i < 8; i++) t += red[i];
        sMean = t * (1.f / DM);
    }
    __syncthreads();
    const float mu = sMean;
    float q = 0.f;
#pragma unroll
    for (int i = 0; i < 4; i++) { float dd = v[i] - mu; q = fmaf(dd, dd, q); }
#pragma unroll
    for (int off = 16; off; off >>= 1) q += __shfl_xor_sync(0xffffffffu, q, off);
    if ((tid & 31) == 0) red[tid >> 5] = q;
    __syncthreads();
    if (tid == 0) {
        float t = 0.f;
        for (int i = 0; i < 8; i++) t += red[i];
        sVar = t * (1.f / DM);
    }
    __syncthreads();
    const float rstd = rsqrtf(sVar + 1e-5f);
#pragma unroll
    for (int i = 0; i < 4; i++) {
        int c = tid + 256*i;
        out[row*DM + c] = (v[i] - mu) * rstd * gw[c] + gb[c];
    }
}

// ---------------------------------------------------------------------------
extern "C" void kernel_launch(void* const* d_in, const int* in_sizes, int n_in,
                              void* d_out, int out_size)
{
    const float* x          = (const float*)d_in[0];
    const float* in_proj_w  = (const float*)d_in[1];
    const float* conv_w     = (const float*)d_in[2];
    const float* conv_b     = (const float*)d_in[3];
    const float* x_proj_w   = (const float*)d_in[4];
    const float* dt_proj_w  = (const float*)d_in[5];
    const float* dt_proj_b  = (const float*)d_in[6];
    const float* A_log      = (const float*)d_in[7];
    const float* Dv         = (const float*)d_in[8];
    const float* out_proj_w = (const float*)d_in[9];
    const float* ln_g       = (const float*)d_in[10];
    const float* ln_b       = (const float*)d_in[11];
    float* out = (float*)d_out;

    float *p_xz, *p_xc, *p_xdbl, *p_dt, *p_y, *p_o;
    cudaGetSymbolAddress((void**)&p_xz,   g_xz);
    cudaGetSymbolAddress((void**)&p_xc,   g_xc);
    cudaGetSymbolAddress((void**)&p_xdbl, g_xdbl);
    cudaGetSymbolAddress((void**)&p_dt,   g_dt);
    cudaGetSymbolAddress((void**)&p_y,    g_y);
    cudaGetSymbolAddress((void**)&p_o,    g_o);

    // G1: xz = x @ in_proj_w^T      [4096,1024] x [4096,1024]^T -> [4096,4096]
    {
        dim3 grid(4096/128, ROWS/128);
        sgemm_nt<128,128,16,8,8,0><<<grid, 256>>>(x, DM, in_proj_w, DM,
                                                  p_xz, 2*DI, DM, nullptr);
    }
    // conv + silu -> g_xc
    conv_silu_kernel<<<(ROWS*DI)/256, 256>>>(conv_w, conv_b);

    // G2: x_dbl = xc @ x_proj_w^T   [4096,2048] x [96,2048]^T -> [4096,96]
    {
        dim3 grid(96/96, ROWS/128);
        sgemm_nt<128,96,16,8,6,0><<<grid, 256>>>(p_xc, DI, x_proj_w, DI,
                                                 p_xdbl, 96, DI, nullptr);
    }
    // G3: dt = softplus(dt_r @ dt_proj_w^T + b)  [4096,64(lda=96)] x [2048,64]^T
    {
        dim3 grid(DI/128, ROWS/128);
        sgemm_nt<128,128,16,8,8,1><<<grid, 256>>>(p_xdbl, 96, dt_proj_w, DTR,
                                                  p_dt, DI, DTR, dt_proj_b);
    }
    // selective scan + gating -> g_y
    scan_kernel<<<64, 256>>>(A_log, Dv);

    // G4: o = y @ out_proj_w^T      [4096,2048] x [1024,2048]^T -> [4096,1024]
    {
        dim3 grid(DM/128, ROWS/128);
        sgemm_nt<128,128,16,8,8,0><<<grid, 256>>>(p_y, DI, out_proj_w, DI,
                                                  p_o, DM, DI, nullptr);
    }
    // residual + layernorm -> out
    ln_kernel<<<ROWS, 256>>>(x, ln_g, ln_b, out);
}

// round 7
// speedup vs baseline: 1.3318x; 1.3318x over previous
#include <cuda_runtime.h>
#include <cuda_bf16.h>
#include <math.h>
#include <stdint.h>

#define DM   1024
#define DI   2048
#define DS   16
#define DTR  64
#define BATCH 2
#define LSEQ 2048
#define ROWS (BATCH*LSEQ)          // 4096 token rows

// ---------------- scratch (device globals; no allocation allowed) ----------
__device__ float g_xz  [ROWS * 2 * DI];   // 4096 x 4096   (xi | z)
__device__ float g_xc  [ROWS * DI];       // conv+silu output (u)
__device__ float g_xdbl[ROWS * 96];       // dt_r(64) | B(16) | C(16)
__device__ float g_dt  [ROWS * DI];       // softplus(dt)
__device__ float g_y   [ROWS * DI];       // gated scan output
__device__ float g_o   [ROWS * DM];       // out_proj result (pre-LN)

// bf16 3-segment split buffers (reused across the 4 GEMMs, sequential)
__device__ __nv_bfloat16 g_a3[ROWS * 3 * DI];      // up to 4096 x 6144
__device__ __nv_bfloat16 g_b3[4096 * 3 * DM];      // up to 4096 x 3072

// ===========================================================================
// helpers
// ===========================================================================
__device__ __forceinline__ uint32_t smem_u32(const void* p){
    uint32_t a;
    asm("{ .reg .u64 t; cvta.to.shared.u64 t, %1; cvt.u32.u64 %0, t; }"
        : "=r"(a) : "l"(p));
    return a;
}
__device__ __forceinline__ void cp16(uint32_t dst, const void* src){
    asm volatile("cp.async.cg.shared.global [%0], [%1], 16;"
                 :: "r"(dst), "l"(src));
}

// Load a [ROWSN x 64] bf16 tile into smem with 128B rows and XOR-8 swizzle.
template<int ROWSN>
__device__ __forceinline__ void load_tile(uint32_t s, const __nv_bfloat16* g,
                                          long ldg, int k0, int tid)
{
#pragma unroll
    for (int i = 0; i < (ROWSN*8)/256; i++) {
        int q = i*256 + tid;
        int r = q >> 3, c = q & 7;
        cp16(s + r*128 + ((c ^ (r & 7)) * 16), g + (long)r*ldg + k0 + c*8);
    }
}

// ===========================================================================
// Split fp32 -> bf16 3-segment layout along K.
// MODE 0 (A): [hi | hi | lo]   MODE 1 (B): [hi | lo | hi]
//   =>  sum over 3K = hi*hi + hi*lo + lo*hi ~ fp32 product
// ===========================================================================
template<int MODE>
__global__ void split3_kernel(const float* __restrict__ src, int srcStride, int K,
                              __nv_bfloat16* __restrict__ dst, int total)
{
    int idx = blockIdx.x * blockDim.x + threadIdx.x;
    if (idx >= total) return;
    int m = idx / K, k = idx - m * K;
    float v = src[(long)m * srcStride + k];
    __nv_bfloat16 hi = __float2bfloat16(v);
    __nv_bfloat16 lo = __float2bfloat16(v - __bfloat162float(hi));
    long base = (long)m * 3 * K;
    if (MODE == 0) {
        dst[base + k] = hi; dst[base + K + k] = hi; dst[base + 2*K + k] = lo;
    } else {
        dst[base + k] = hi; dst[base + K + k] = lo; dst[base + 2*K + k] = hi;
    }
}

// ===========================================================================
// Tensor-core GEMM via mma.sync (HMMA):  C[M,N] = epi( A3[M,K3] * B3[N,K3]^T )
// 256 threads = 8 warps as 2(m) x 4(n).  Block tile 128 x BN, BK = 64 bf16.
// Warp tile 64 x WN (WN = BN/4).  EPI 0: none.  EPI 1: softplus(v+bias[col]).
// ===========================================================================
template<int BN, int WN, int EPI>
__global__ void __launch_bounds__(256)
gemm_mma(const __nv_bfloat16* __restrict__ A, const __nv_bfloat16* __restrict__ B,
         float* __restrict__ C, int ldc, int K3, const float* __restrict__ bias)
{
    constexpr int NT = WN / 8;               // n-atoms per warp
    extern __shared__ char smem[];
    uint32_t sb = (smem_u32(smem) + 127u) & ~127u;
    const uint32_t sA0 = sb;
    const uint32_t sA1 = sb + 128*128;
    const uint32_t sB0 = sb + 2*128*128;
    const uint32_t sB1 = sB0 + BN*128;

    const int tid  = threadIdx.x;
    const int wid  = tid >> 5, lane = tid & 31;
    const int wm   = wid & 1;                // 0..1  (64 rows each)
    const int wn   = wid >> 1;               // 0..3  (WN cols each)
    const int rowBase = blockIdx.y * 128;
    const int colBase = blockIdx.x * BN;
    const __nv_bfloat16* Ag = A + (long)rowBase * K3;
    const __nv_bfloat16* Bg = B + (long)colBase * K3;

    float d[4][NT][4];
#pragma unroll
    for (int mt = 0; mt < 4; mt++)
#pragma unroll
        for (int nt = 0; nt < NT; nt++)
#pragma unroll
            for (int e = 0; e < 4; e++) d[mt][nt][e] = 0.f;

    const int nk = K3 / 64;
    load_tile<128>(sA0, Ag, K3, 0, tid);
    load_tile<BN >(sB0, Bg, K3, 0, tid);
    asm volatile("cp.async.commit_group;" ::: "memory");
    if (nk > 1) {
        load_tile<128>(sA1, Ag, K3, 64, tid);
        load_tile<BN >(sB1, Bg, K3, 64, tid);
    }
    asm volatile("cp.async.commit_group;" ::: "memory");

    for (int i = 0; i < nk; i++) {
        if (i + 1 < nk) asm volatile("cp.async.wait_group 1;" ::: "memory");
        else            asm volatile("cp.async.wait_group 0;" ::: "memory");
        __syncthreads();
        const uint32_t sA = (i & 1) ? sA1 : sA0;
        const uint32_t sB = (i & 1) ? sB1 : sB0;

#pragma unroll
        for (int ks = 0; ks < 4; ks++) {     // 4 x K16 per BK=64 stage
            uint32_t a[4][4], b[NT][2];
#pragma unroll
            for (int mt = 0; mt < 4; mt++) {
                int r = wm*64 + mt*16 + (lane & 15);
                int c = ks*2 + (lane >> 4);
                uint32_t addr = sA + r*128 + ((c ^ (r & 7)) * 16);
                asm volatile("ldmatrix.sync.aligned.m8n8.x4.shared.b16 "
                             "{%0,%1,%2,%3}, [%4];"
                             : "=r"(a[mt][0]), "=r"(a[mt][1]),
                               "=r"(a[mt][2]), "=r"(a[mt][3]) : "r"(addr));
            }
#pragma unroll
            for (int nt = 0; nt < NT; nt++) {
                int r = wn*WN + nt*8 + (lane & 7);
                int c = ks*2 + ((lane >> 3) & 1);
                uint32_t addr = sB + r*128 + ((c ^ (r & 7)) * 16);
                asm volatile("ldmatrix.sync.aligned.m8n8.x2.shared.b16 "
                             "{%0,%1}, [%2];"
                             : "=r"(b[nt][0]), "=r"(b[nt][1]) : "r"(addr));
            }
#pragma unroll
            for (int mt = 0; mt < 4; mt++)
#pragma unroll
                for (int nt = 0; nt < NT; nt++)
                    asm volatile(
                        "mma.sync.aligned.m16n8k16.row.col.f32.bf16.bf16.f32 "
                        "{%0,%1,%2,%3}, {%4,%5,%6,%7}, {%8,%9}, {%0,%1,%2,%3};"
                        : "+f"(d[mt][nt][0]), "+f"(d[mt][nt][1]),
                          "+f"(d[mt][nt][2]), "+f"(d[mt][nt][3])
                        : "r"(a[mt][0]), "r"(a[mt][1]),
                          "r"(a[mt][2]), "r"(a[mt][3]),
                          "r"(b[nt][0]), "r"(b[nt][1]));
        }
        __syncthreads();
        if (i + 2 < nk) {
            const uint32_t dA = (i & 1) ? sA1 : sA0;
            const uint32_t dB = (i & 1) ? sB1 : sB0;
            load_tile<128>(dA, Ag, K3, (i+2)*64, tid);
            load_tile<BN >(dB, Bg, K3, (i+2)*64, tid);
            asm volatile("cp.async.commit_group;" ::: "memory");
        }
    }

    // epilogue
#pragma unroll
    for (int mt = 0; mt < 4; mt++) {
        int r0 = rowBase + wm*64 + mt*16 + (lane >> 2);
#pragma unroll
        for (int nt = 0; nt < NT; nt++) {
            int c0 = colBase + wn*WN + nt*8 + (lane & 3)*2;
            float v0 = d[mt][nt][0], v1 = d[mt][nt][1];
            float v2 = d[mt][nt][2], v3 = d[mt][nt][3];
            if (EPI == 1) {
                v0 += bias[c0];   v1 += bias[c0+1];
                v2 += bias[c0];   v3 += bias[c0+1];
                v0 = fmaxf(v0,0.f) + log1pf(__expf(-fabsf(v0)));
                v1 = fmaxf(v1,0.f) + log1pf(__expf(-fabsf(v1)));
                v2 = fmaxf(v2,0.f) + log1pf(__expf(-fabsf(v2)));
                v3 = fmaxf(v3,0.f) + log1pf(__expf(-fabsf(v3)));
            }
            *reinterpret_cast<float2*>(&C[(long)r0*ldc + c0])     = make_float2(v0, v1);
            *reinterpret_cast<float2*>(&C[(long)(r0+8)*ldc + c0]) = make_float2(v2, v3);
        }
    }
}

// ---------------------------------------------------------------------------
// Depthwise causal conv (k=4) + bias + SiLU.  Reads xi = g_xz[:, :DI].
// ---------------------------------------------------------------------------
__global__ void conv_silu_kernel(const float* __restrict__ cw,
                                 const float* __restrict__ cb)
{
    int idx = blockIdx.x * blockDim.x + threadIdx.x;
    if (idx >= ROWS * DI) return;
    int d = idx % DI;
    int t = (idx / DI) % LSEQ;
    int b = idx / (DI * LSEQ);
    float acc = cb[d];
#pragma unroll
    for (int j = 0; j < 4; j++) {
        int tt = t - 3 + j;
        if (tt >= 0)
            acc = fmaf(cw[d*4 + j], g_xz[(b*LSEQ + tt)*(2*DI) + d], acc);
    }
    g_xc[idx] = acc / (1.f + __expf(-acc));   // silu
}

// ---------------------------------------------------------------------------
// Selective scan. 4 threads per channel, 4 states per thread.
// ---------------------------------------------------------------------------
__global__ void __launch_bounds__(256)
scan_kernel(const float* __restrict__ Alog, const float* __restrict__ Dv)
{
    const int b     = blockIdx.x >> 5;
    const int dBase = (blockIdx.x & 31) * 64;
    const int tid   = threadIdx.x;
    const int d     = dBase + (tid >> 2);
    const int j     = tid & 3;

    float A[4];
#pragma unroll
    for (int s = 0; s < 4; s++) A[s] = -__expf(Alog[d*DS + j*4 + s]);

    float h[4] = {0.f, 0.f, 0.f, 0.f};
    const float Dd = Dv[d];

    __shared__ float sB[64][16];
    __shared__ float sC[64][16];

    const float* __restrict__ xdbl = g_xdbl + b*LSEQ*96;
    const float* __restrict__ dtp  = g_dt   + b*LSEQ*DI;
    const float* __restrict__ up   = g_xc   + b*LSEQ*DI;
    const float* __restrict__ zp   = g_xz   + b*LSEQ*(2*DI) + DI;
    float*       __restrict__ yp   = g_y    + b*LSEQ*DI;

    for (int t0 = 0; t0 < LSEQ; t0 += 64) {
        __syncthreads();
        for (int i = tid; i < 64*32; i += 256) {
            int tl = i >> 5, c = i & 31;
            float v = xdbl[(t0 + tl)*96 + 64 + c];
            if (c < 16) sB[tl][c] = v; else sC[tl][c - 16] = v;
        }
        __syncthreads();

#pragma unroll 4
        for (int tl = 0; tl < 64; tl++) {
            const int t  = t0 + tl;
            const float dt = dtp[t*DI + d];
            const float u  = up [t*DI + d];
            const float du = dt * u;
            float acc = 0.f;
#pragma unroll
            for (int s = 0; s < 4; s++) {
                float dA = __expf(dt * A[s]);
                h[s] = fmaf(dA, h[s], du * sB[tl][j*4 + s]);
                acc  = fmaf(h[s], sC[tl][j*4 + s], acc);
            }
            acc += __shfl_xor_sync(0xffffffffu, acc, 1);
            acc += __shfl_xor_sync(0xffffffffu, acc, 2);
            if (j == 0) {
                float z  = zp[t*(2*DI) + d];
                float yv = fmaf(Dd, u, acc);
                yv *= z / (1.f + __expf(-z));
                yp[t*DI + d] = yv;
            }
        }
    }
}

// ---------------------------------------------------------------------------
// Residual + LayerNorm over 1024.  out = LN(g_o + x) * g + b
// ---------------------------------------------------------------------------
__global__ void __launch_bounds__(256)
ln_kernel(const float* __restrict__ x, const float* __restrict__ gw,
          const float* __restrict__ gb, float* __restrict__ out)
{
    const int row = blockIdx.x;
    const int tid = threadIdx.x;
    const float* o  = g_o + row*DM;
    const float* xr = x   + row*DM;

    float v[4];
    float s = 0.f;
#pragma unroll
    for (int i = 0; i < 4; i++) {
        int c = tid + 256*i;
        v[i] = o[c] + xr[c];
        s += v[i];
    }
    __shared__ float red[8];
    __shared__ float sMean, sVar;
#pragma unroll
    for (int off = 16; off; off >>= 1) s += __shfl_xor_sync(0xffffffffu, s, off);
    if ((tid & 31) == 0) red[tid >> 5] = s;
    __syncthreads();
    if (tid == 0) {
        float t = 0.f;
        for (int i = 0; i < 8; i++) t += red[i];
        sMean = t * (1.f / DM);
    }
    __syncthreads();
    const float mu = sMean;
    float q = 0.f;
#pragma unroll
    for (int i = 0; i < 4; i++) { float dd = v[i] - mu; q = fmaf(dd, dd, q); }
#pragma unroll
    for (int off = 16; off; off >>= 1) q += __shfl_xor_sync(0xffffffffu, q, off);
    if ((tid & 31) == 0) red[tid >> 5] = q;
    __syncthreads();
    if (tid == 0) {
        float t = 0.f;
        for (int i = 0; i < 8; i++) t += red[i];
        sVar = t * (1.f / DM);
    }
    __syncthreads();
    const float rstd = rsqrtf(sVar + 1e-5f);
#pragma unroll
    for (int i = 0; i < 4; i++) {
        int c = tid + 256*i;
        out[row*DM + c] = (v[i] - mu) * rstd * gw[c] + gb[c];
    }
}

// ---------------------------------------------------------------------------
extern "C" void kernel_launch(void* const* d_in, const int* in_sizes, int n_in,
                              void* d_out, int out_size)
{
    const float* x          = (const float*)d_in[0];
    const float* in_proj_w  = (const float*)d_in[1];
    const float* conv_w     = (const float*)d_in[2];
    const float* conv_b     = (const float*)d_in[3];
    const float* x_proj_w   = (const float*)d_in[4];
    const float* dt_proj_w  = (const float*)d_in[5];
    const float* dt_proj_b  = (const float*)d_in[6];
    const float* A_log      = (const float*)d_in[7];
    const float* Dv         = (const float*)d_in[8];
    const float* out_proj_w = (const float*)d_in[9];
    const float* ln_g       = (const float*)d_in[10];
    const float* ln_b       = (const float*)d_in[11];
    float* out = (float*)d_out;

    float *p_xz, *p_xc, *p_xdbl, *p_dt, *p_y, *p_o;
    __nv_bfloat16 *p_a3, *p_b3;
    cudaGetSymbolAddress((void**)&p_xz,   g_xz);
    cudaGetSymbolAddress((void**)&p_xc,   g_xc);
    cudaGetSymbolAddress((void**)&p_xdbl, g_xdbl);
    cudaGetSymbolAddress((void**)&p_dt,   g_dt);
    cudaGetSymbolAddress((void**)&p_y,    g_y);
    cudaGetSymbolAddress((void**)&p_o,    g_o);
    cudaGetSymbolAddress((void**)&p_a3,   g_a3);
    cudaGetSymbolAddress((void**)&p_b3,   g_b3);

    // dynamic smem: A double-buf 32KB + B double-buf
    const int SM128 = 128 + 2*128*128 + 2*128*128;   // 65664
    const int SM32  = 128 + 2*128*128 + 2*32*128;    // 41088
    cudaFuncSetAttribute((const void*)gemm_mma<128,32,0>,
                         cudaFuncAttributeMaxDynamicSharedMemorySize, SM128);
    cudaFuncSetAttribute((const void*)gemm_mma<128,32,1>,
                         cudaFuncAttributeMaxDynamicSharedMemorySize, SM128);
    cudaFuncSetAttribute((const void*)gemm_mma<32,8,0>,
                         cudaFuncAttributeMaxDynamicSharedMemorySize, SM32);

    // ---- G1: xz = x @ in_proj_w^T   [4096,1024]x[4096,1024]^T -> [4096,4096]
    {
        int tA = ROWS*DM, tB = 4096*DM;
        split3_kernel<0><<<(tA+255)/256, 256>>>(x,         DM, DM, p_a3, tA);
        split3_kernel<1><<<(tB+255)/256, 256>>>(in_proj_w, DM, DM, p_b3, tB);
        dim3 grid(4096/128, ROWS/128);
        gemm_mma<128,32,0><<<grid, 256, SM128>>>(p_a3, p_b3, p_xz, 4096, 3*DM, nullptr);
    }
    // ---- conv + silu -> g_xc
    conv_silu_kernel<<<(ROWS*DI)/256, 256>>>(conv_w, conv_b);

    // ---- G2: x_dbl = xc @ x_proj_w^T  [4096,2048]x[96,2048]^T -> [4096,96]
    {
        int tA = ROWS*DI, tB = 96*DI;
        split3_kernel<0><<<(tA+255)/256, 256>>>(p_xc,     DI, DI, p_a3, tA);
        split3_kernel<1><<<(tB+255)/256, 256>>>(x_proj_w, DI, DI, p_b3, tB);
        dim3 grid(96/32, ROWS/128);
        gemm_mma<32,8,0><<<grid, 256, SM32>>>(p_a3, p_b3, p_xdbl, 96, 3*DI, nullptr);
    }
    // ---- G3: dt = softplus(dt_r @ dt_proj_w^T + b)  [4096,64]x[2048,64]^T
    {
        int tA = ROWS*DTR, tB = DI*DTR;
        split3_kernel<0><<<(tA+255)/256, 256>>>(p_xdbl,   96,  DTR, p_a3, tA);
        split3_kernel<1><<<(tB+255)/256, 256>>>(dt_proj_w, DTR, DTR, p_b3, tB);
        dim3 grid(DI/128, ROWS/128);
        gemm_mma<128,32,1><<<grid, 256, SM128>>>(p_a3, p_b3, p_dt, DI, 3*DTR, dt_proj_b);
    }
    // ---- selective scan + gating -> g_y
    scan_kernel<<<64, 256>>>(A_log, Dv);

    // ---- G4: o = y @ out_proj_w^T  [4096,2048]x[1024,2048]^T -> [4096,1024]
    {
        int tA = ROWS*DI, tB = DM*DI;
        split3_kernel<0><<<(tA+255)/256, 256>>>(p_y,        DI, DI, p_a3, tA);
        split3_kernel<1><<<(tB+255)/256, 256>>>(out_proj_w, DI, DI, p_b3, tB);
        dim3 grid(DM/128, ROWS/128);
        gemm_mma<128,32,0><<<grid, 256, SM128>>>(p_a3, p_b3, p_o, DM, 3*DI, nullptr);
    }
    // ---- residual + layernorm -> out
    ln_kernel<<<ROWS, 256>>>(x, ln_g, ln_b, out);
}

// round 8
// speedup vs baseline: 1.3578x; 1.0196x over previous
#include <cuda_runtime.h>
#include <cuda_bf16.h>
#include <math.h>
#include <stdint.h>

#define DM   1024
#define DI   2048
#define DS   16
#define DTR  64
#define BATCH 2
#define LSEQ 2048
#define ROWS (BATCH*LSEQ)          // 4096 token rows

// ---------------- scratch (device globals; no allocation allowed) ----------
__device__ float g_xz  [ROWS * 2 * DI];   // 4096 x 4096   (xi | z)
__device__ float g_xc  [ROWS * DI];       // conv+silu output (u)
__device__ float g_xdbl[ROWS * 96];       // dt_r(64) | B(16) | C(16)
__device__ float g_dt  [ROWS * DI];       // softplus(dt)
__device__ float g_y   [ROWS * DI];       // gated scan output
__device__ float g_o   [ROWS * DM];       // out_proj result (pre-LN)

// bf16 3-segment split buffers (reused across the 4 GEMMs, sequential)
__device__ __nv_bfloat16 g_a3[ROWS * 3 * DI];      // up to 4096 x 6144
__device__ __nv_bfloat16 g_b3[4096 * 3 * DM];      // up to 4096 x 3072

// ===========================================================================
// helpers
// ===========================================================================
__device__ __forceinline__ uint32_t smem_u32(const void* p){
    uint32_t a;
    asm("{ .reg .u64 t; cvta.to.shared.u64 t, %1; cvt.u32.u64 %0, t; }"
        : "=r"(a) : "l"(p));
    return a;
}
__device__ __forceinline__ void cp16(uint32_t dst, const void* src){
    asm volatile("cp.async.cg.shared.global [%0], [%1], 16;"
                 :: "r"(dst), "l"(src));
}

// Load a [ROWSN x 64] bf16 tile into smem with 128B rows and XOR-8 swizzle.
template<int ROWSN>
__device__ __forceinline__ void load_tile(uint32_t s, const __nv_bfloat16* g,
                                          long ldg, int k0, int tid)
{
#pragma unroll
    for (int i = 0; i < (ROWSN*8)/256; i++) {
        int q = i*256 + tid;
        int r = q >> 3, c = q & 7;
        cp16(s + r*128 + ((c ^ (r & 7)) * 16), g + (long)r*ldg + k0 + c*8);
    }
}

// ===========================================================================
// Split fp32 -> bf16 3-segment layout along K.
// MODE 0 (A): [hi | hi | lo]   MODE 1 (B): [hi | lo | hi]
//   =>  sum over 3K = hi*hi + hi*lo + lo*hi ~ fp32 product
// ===========================================================================
template<int MODE>
__global__ void split3_kernel(const float* __restrict__ src, int srcStride, int K,
                              __nv_bfloat16* __restrict__ dst, int total)
{
    int idx = blockIdx.x * blockDim.x + threadIdx.x;
    if (idx >= total) return;
    int m = idx / K, k = idx - m * K;
    float v = src[(long)m * srcStride + k];
    __nv_bfloat16 hi = __float2bfloat16(v);
    __nv_bfloat16 lo = __float2bfloat16(v - __bfloat162float(hi));
    long base = (long)m * 3 * K;
    if (MODE == 0) {
        dst[base + k] = hi; dst[base + K + k] = hi; dst[base + 2*K + k] = lo;
    } else {
        dst[base + k] = hi; dst[base + K + k] = lo; dst[base + 2*K + k] = hi;
    }
}

// ===========================================================================
// Tensor-core GEMM via mma.sync (HMMA):  C[M,N] = epi( A3[M,K3] * B3[N,K3]^T )
// 256 threads = 8 warps as 2(m) x 4(n).  Block tile 128 x BN, BK = 64 bf16.
// 3-stage circular cp.async pipeline, ONE __syncthreads per stage.
// Warp tile 64 x WN.  EPI 0: none.  EPI 1: softplus(v+bias[col]).
// ===========================================================================
template<int BN, int WN, int EPI>
__global__ void __launch_bounds__(256)
gemm_mma(const __nv_bfloat16* __restrict__ A, const __nv_bfloat16* __restrict__ B,
         float* __restrict__ C, int ldc, int K3, const float* __restrict__ bias)
{
    constexpr int NT = WN / 8;               // n-atoms per warp
    constexpr int STAGE = 128*128 + BN*128;  // A tile + B tile bytes
    extern __shared__ char smem[];
    uint32_t sb = (smem_u32(smem) + 127u) & ~127u;

    const int tid  = threadIdx.x;
    const int wid  = tid >> 5, lane = tid & 31;
    const int wm   = wid & 1;                // 0..1  (64 rows each)
    const int wn   = wid >> 1;               // 0..3  (WN cols each)
    const int rowBase = blockIdx.y * 128;
    const int colBase = blockIdx.x * BN;
    const __nv_bfloat16* Ag = A + (long)rowBase * K3;
    const __nv_bfloat16* Bg = B + (long)colBase * K3;

    float d[4][NT][4];
#pragma unroll
    for (int mt = 0; mt < 4; mt++)
#pragma unroll
        for (int nt = 0; nt < NT; nt++)
#pragma unroll
            for (int e = 0; e < 4; e++) d[mt][nt][e] = 0.f;

    const int nk = K3 / 64;

    // prefetch stages 0 and 1
    load_tile<128>(sb,            Ag, K3, 0, tid);
    load_tile<BN >(sb + 128*128,  Bg, K3, 0, tid);
    asm volatile("cp.async.commit_group;" ::: "memory");
    if (nk > 1) {
        load_tile<128>(sb + STAGE,           Ag, K3, 64, tid);
        load_tile<BN >(sb + STAGE + 128*128, Bg, K3, 64, tid);
        asm volatile("cp.async.commit_group;" ::: "memory");
    }

    int slot = 0;                            // slot of current stage (i % 3)
    for (int i = 0; i < nk; i++) {
        if (i + 1 < nk) asm volatile("cp.async.wait_group 1;" ::: "memory");
        else            asm volatile("cp.async.wait_group 0;" ::: "memory");
        __syncthreads();

        // prefetch stage i+2 into slot (i+2)%3 (freed: held stage i-1)
        if (i + 2 < nk) {
            int ps = slot + 2; if (ps >= 3) ps -= 3;
            load_tile<128>(sb + ps*STAGE,           Ag, K3, (i+2)*64, tid);
            load_tile<BN >(sb + ps*STAGE + 128*128, Bg, K3, (i+2)*64, tid);
            asm volatile("cp.async.commit_group;" ::: "memory");
        }

        const uint32_t sA = sb + slot*STAGE;
        const uint32_t sB = sA + 128*128;

#pragma unroll
        for (int ks = 0; ks < 4; ks++) {     // 4 x K16 per BK=64 stage
            uint32_t a[4][4], b[NT][2];
#pragma unroll
            for (int mt = 0; mt < 4; mt++) {
                int r = wm*64 + mt*16 + (lane & 15);
                int c = ks*2 + (lane >> 4);
                uint32_t addr = sA + r*128 + ((c ^ (r & 7)) * 16);
                asm volatile("ldmatrix.sync.aligned.m8n8.x4.shared.b16 "
                             "{%0,%1,%2,%3}, [%4];"
                             : "=r"(a[mt][0]), "=r"(a[mt][1]),
                               "=r"(a[mt][2]), "=r"(a[mt][3]) : "r"(addr));
            }
            if constexpr ((NT & 1) == 0) {
                // paired x4: two n-atoms per ldmatrix
#pragma unroll
                for (int nt = 0; nt < NT; nt += 2) {
                    int g     = lane >> 3;             // 0..3
                    int ntq   = nt + (g >> 1);
                    int khalf = g & 1;
                    int r = wn*WN + ntq*8 + (lane & 7);
                    int c = ks*2 + khalf;
                    uint32_t addr = sB + r*128 + ((c ^ (r & 7)) * 16);
                    asm volatile("ldmatrix.sync.aligned.m8n8.x4.shared.b16 "
                                 "{%0,%1,%2,%3}, [%4];"
                                 : "=r"(b[nt][0]),   "=r"(b[nt][1]),
                                   "=r"(b[nt+1][0]), "=r"(b[nt+1][1])
                                 : "r"(addr));
                }
            } else {
#pragma unroll
                for (int nt = 0; nt < NT; nt++) {
                    int r = wn*WN + nt*8 + (lane & 7);
                    int c = ks*2 + ((lane >> 3) & 1);
                    uint32_t addr = sB + r*128 + ((c ^ (r & 7)) * 16);
                    asm volatile("ldmatrix.sync.aligned.m8n8.x2.shared.b16 "
                                 "{%0,%1}, [%2];"
                                 : "=r"(b[nt][0]), "=r"(b[nt][1]) : "r"(addr));
                }
            }
#pragma unroll
            for (int mt = 0; mt < 4; mt++)
#pragma unroll
                for (int nt = 0; nt < NT; nt++)
                    asm volatile(
                        "mma.sync.aligned.m16n8k16.row.col.f32.bf16.bf16.f32 "
                        "{%0,%1,%2,%3}, {%4,%5,%6,%7}, {%8,%9}, {%0,%1,%2,%3};"
                        : "+f"(d[mt][nt][0]), "+f"(d[mt][nt][1]),
                          "+f"(d[mt][nt][2]), "+f"(d[mt][nt][3])
                        : "r"(a[mt][0]), "r"(a[mt][1]),
                          "r"(a[mt][2]), "r"(a[mt][3]),
                          "r"(b[nt][0]), "r"(b[nt][1]));
        }
        if (++slot >= 3) slot -= 3;
    }

    // epilogue
#pragma unroll
    for (int mt = 0; mt < 4; mt++) {
        int r0 = rowBase + wm*64 + mt*16 + (lane >> 2);
#pragma unroll
        for (int nt = 0; nt < NT; nt++) {
            int c0 = colBase + wn*WN + nt*8 + (lane & 3)*2;
            float v0 = d[mt][nt][0], v1 = d[mt][nt][1];
            float v2 = d[mt][nt][2], v3 = d[mt][nt][3];
            if (EPI == 1) {
                v0 += bias[c0];   v1 += bias[c0+1];
                v2 += bias[c0];   v3 += bias[c0+1];
                v0 = fmaxf(v0,0.f) + log1pf(__expf(-fabsf(v0)));
                v1 = fmaxf(v1,0.f) + log1pf(__expf(-fabsf(v1)));
                v2 = fmaxf(v2,0.f) + log1pf(__expf(-fabsf(v2)));
                v3 = fmaxf(v3,0.f) + log1pf(__expf(-fabsf(v3)));
            }
            *reinterpret_cast<float2*>(&C[(long)r0*ldc + c0])     = make_float2(v0, v1);
            *reinterpret_cast<float2*>(&C[(long)(r0+8)*ldc + c0]) = make_float2(v2, v3);
        }
    }
}

// ---------------------------------------------------------------------------
// Depthwise causal conv (k=4) + bias + SiLU.  Reads xi = g_xz[:, :DI].
// ---------------------------------------------------------------------------
__global__ void conv_silu_kernel(const float* __restrict__ cw,
                                 const float* __restrict__ cb)
{
    int idx = blockIdx.x * blockDim.x + threadIdx.x;
    if (idx >= ROWS * DI) return;
    int d = idx % DI;
    int t = (idx / DI) % LSEQ;
    int b = idx / (DI * LSEQ);
    float acc = cb[d];
#pragma unroll
    for (int j = 0; j < 4; j++) {
        int tt = t - 3 + j;
        if (tt >= 0)
            acc = fmaf(cw[d*4 + j], g_xz[(b*LSEQ + tt)*(2*DI) + d], acc);
    }
    g_xc[idx] = acc / (1.f + __expf(-acc));   // silu
}

// ---------------------------------------------------------------------------
// Selective scan. 4 threads per channel, 4 states per thread.
// ---------------------------------------------------------------------------
__global__ void __launch_bounds__(256)
scan_kernel(const float* __restrict__ Alog, const float* __restrict__ Dv)
{
    const int b     = blockIdx.x >> 5;
    const int dBase = (blockIdx.x & 31) * 64;
    const int tid   = threadIdx.x;
    const int d     = dBase + (tid >> 2);
    const int j     = tid & 3;

    float A[4];
#pragma unroll
    for (int s = 0; s < 4; s++) A[s] = -__expf(Alog[d*DS + j*4 + s]);

    float h[4] = {0.f, 0.f, 0.f, 0.f};
    const float Dd = Dv[d];

    __shared__ float sB[64][16];
    __shared__ float sC[64][16];

    const float* __restrict__ xdbl = g_xdbl + b*LSEQ*96;
    const float* __restrict__ dtp  = g_dt   + b*LSEQ*DI;
    const float* __restrict__ up   = g_xc   + b*LSEQ*DI;
    const float* __restrict__ zp   = g_xz   + b*LSEQ*(2*DI) + DI;
    float*       __restrict__ yp   = g_y    + b*LSEQ*DI;

    for (int t0 = 0; t0 < LSEQ; t0 += 64) {
        __syncthreads();
        for (int i = tid; i < 64*32; i += 256) {
            int tl = i >> 5, c = i & 31;
            float v = xdbl[(t0 + tl)*96 + 64 + c];
            if (c < 16) sB[tl][c] = v; else sC[tl][c - 16] = v;
        }
        __syncthreads();

#pragma unroll 4
        for (int tl = 0; tl < 64; tl++) {
            const int t  = t0 + tl;
            const float dt = dtp[t*DI + d];
            const float u  = up [t*DI + d];
            const float du = dt * u;
            float acc = 0.f;
#pragma unroll
            for (int s = 0; s < 4; s++) {
                float dA = __expf(dt * A[s]);
                h[s] = fmaf(dA, h[s], du * sB[tl][j*4 + s]);
                acc  = fmaf(h[s], sC[tl][j*4 + s], acc);
            }
            acc += __shfl_xor_sync(0xffffffffu, acc, 1);
            acc += __shfl_xor_sync(0xffffffffu, acc, 2);
            if (j == 0) {
                float z  = zp[t*(2*DI) + d];
                float yv = fmaf(Dd, u, acc);
                yv *= z / (1.f + __expf(-z));
                yp[t*DI + d] = yv;
            }
        }
    }
}

// ---------------------------------------------------------------------------
// Residual + LayerNorm over 1024.  out = LN(g_o + x) * g + b
// ---------------------------------------------------------------------------
__global__ void __launch_bounds__(256)
ln_kernel(const float* __restrict__ x, const float* __restrict__ gw,
          const float* __restrict__ gb, float* __restrict__ out)
{
    const int row = blockIdx.x;
    const int tid = threadIdx.x;
    const float* o  = g_o + row*DM;
    const float* xr = x   + row*DM;

    float v[4];
    float s = 0.f;
#pragma unroll
    for (int i = 0; i < 4; i++) {
        int c = tid + 256*i;
        v[i] = o[c] + xr[c];
        s += v[i];
    }
    __shared__ float red[8];
    __shared__ float sMean, sVar;
#pragma unroll
    for (int off = 16; off; off >>= 1) s += __shfl_xor_sync(0xffffffffu, s, off);
    if ((tid & 31) == 0) red[tid >> 5] = s;
    __syncthreads();
    if (tid == 0) {
        float t = 0.f;
        for (int i = 0; i < 8; i++) t += red[i];
        sMean = t * (1.f / DM);
    }
    __syncthreads();
    const float mu = sMean;
    float q = 0.f;
#pragma unroll
    for (int i = 0; i < 4; i++) { float dd = v[i] - mu; q = fmaf(dd, dd, q); }
#pragma unroll
    for (int off = 16; off; off >>= 1) q += __shfl_xor_sync(0xffffffffu, q, off);
    if ((tid & 31) == 0) red[tid >> 5] = q;
    __syncthreads();
    if (tid == 0) {
        float t = 0.f;
        for (int i = 0; i < 8; i++) t += red[i];
        sVar = t * (1.f / DM);
    }
    __syncthreads();
    const float rstd = rsqrtf(sVar + 1e-5f);
#pragma unroll
    for (int i = 0; i < 4; i++) {
        int c = tid + 256*i;
        out[row*DM + c] = (v[i] - mu) * rstd * gw[c] + gb[c];
    }
}

// ---------------------------------------------------------------------------
extern "C" void kernel_launch(void* const* d_in, const int* in_sizes, int n_in,
                              void* d_out, int out_size)
{
    const float* x          = (const float*)d_in[0];
    const float* in_proj_w  = (const float*)d_in[1];
    const float* conv_w     = (const float*)d_in[2];
    const float* conv_b     = (const float*)d_in[3];
    const float* x_proj_w   = (const float*)d_in[4];
    const float* dt_proj_w  = (const float*)d_in[5];
    const float* dt_proj_b  = (const float*)d_in[6];
    const float* A_log      = (const float*)d_in[7];
    const float* Dv         = (const float*)d_in[8];
    const float* out_proj_w = (const float*)d_in[9];
    const float* ln_g       = (const float*)d_in[10];
    const float* ln_b       = (const float*)d_in[11];
    float* out = (float*)d_out;

    float *p_xz, *p_xc, *p_xdbl, *p_dt, *p_y, *p_o;
    __nv_bfloat16 *p_a3, *p_b3;
    cudaGetSymbolAddress((void**)&p_xz,   g_xz);
    cudaGetSymbolAddress((void**)&p_xc,   g_xc);
    cudaGetSymbolAddress((void**)&p_xdbl, g_xdbl);
    cudaGetSymbolAddress((void**)&p_dt,   g_dt);
    cudaGetSymbolAddress((void**)&p_y,    g_y);
    cudaGetSymbolAddress((void**)&p_o,    g_o);
    cudaGetSymbolAddress((void**)&p_a3,   g_a3);
    cudaGetSymbolAddress((void**)&p_b3,   g_b3);

    // dynamic smem: 3 stages x (A 16KB + B BN*128B) + align pad
    const int SM128 = 128 + 3*(128*128 + 128*128);   // 98432
    const int SM32  = 128 + 3*(128*128 + 32*128);    // 61568
    cudaFuncSetAttribute((const void*)gemm_mma<128,32,0>,
                         cudaFuncAttributeMaxDynamicSharedMemorySize, SM128);
    cudaFuncSetAttribute((const void*)gemm_mma<128,32,1>,
                         cudaFuncAttributeMaxDynamicSharedMemorySize, SM128);
    cudaFuncSetAttribute((const void*)gemm_mma<32,8,0>,
                         cudaFuncAttributeMaxDynamicSharedMemorySize, SM32);

    // ---- G1: xz = x @ in_proj_w^T   [4096,1024]x[4096,1024]^T -> [4096,4096]
    {
        int tA = ROWS*DM, tB = 4096*DM;
        split3_kernel<0><<<(tA+255)/256, 256>>>(x,         DM, DM, p_a3, tA);
        split3_kernel<1><<<(tB+255)/256, 256>>>(in_proj_w, DM, DM, p_b3, tB);
        dim3 grid(4096/128, ROWS/128);
        gemm_mma<128,32,0><<<grid, 256, SM128>>>(p_a3, p_b3, p_xz, 4096, 3*DM, nullptr);
    }
    // ---- conv + silu -> g_xc
    conv_silu_kernel<<<(ROWS*DI)/256, 256>>>(conv_w, conv_b);

    // ---- G2: x_dbl = xc @ x_proj_w^T  [4096,2048]x[96,2048]^T -> [4096,96]
    {
        int tA = ROWS*DI, tB = 96*DI;
        split3_kernel<0><<<(tA+255)/256, 256>>>(p_xc,     DI, DI, p_a3, tA);
        split3_kernel<1><<<(tB+255)/256, 256>>>(x_proj_w, DI, DI, p_b3, tB);
        dim3 grid(96/32, ROWS/128);
        gemm_mma<32,8,0><<<grid, 256, SM32>>>(p_a3, p_b3, p_xdbl, 96, 3*DI, nullptr);
    }
    // ---- G3: dt = softplus(dt_r @ dt_proj_w^T + b)  [4096,64]x[2048,64]^T
    {
        int tA = ROWS*DTR, tB = DI*DTR;
        split3_kernel<0><<<(tA+255)/256, 256>>>(p_xdbl,   96,  DTR, p_a3, tA);
        split3_kernel<1><<<(tB+255)/256, 256>>>(dt_proj_w, DTR, DTR, p_b3, tB);
        dim3 grid(DI/128, ROWS/128);
        gemm_mma<128,32,1><<<grid, 256, SM128>>>(p_a3, p_b3, p_dt, DI, 3*DTR, dt_proj_b);
    }
    // ---- selective scan + gating -> g_y
    scan_kernel<<<64, 256>>>(A_log, Dv);

    // ---- G4: o = y @ out_proj_w^T  [4096,2048]x[1024,2048]^T -> [4096,1024]
    {
        int tA = ROWS*DI, tB = DM*DI;
        split3_kernel<0><<<(tA+255)/256, 256>>>(p_y,        DI, DI, p_a3, tA);
        split3_kernel<1><<<(tB+255)/256, 256>>>(out_proj_w, DI, DI, p_b3, tB);
        dim3 grid(DM/128, ROWS/128);
        gemm_mma<128,32,0><<<grid, 256, SM128>>>(p_a3, p_b3, p_o, DM, 3*DI, nullptr);
    }
    // ---- residual + layernorm -> out
    ln_kernel<<<ROWS, 256>>>(x, ln_g, ln_b, out);
}